// round 1
// baseline (speedup 1.0000x reference)
#include <cuda_runtime.h>
#include <cuda_bf16.h>

// Direct 7x7 conv, C=1: out[b,f,y,x] = sum_{ky,kx} in[b,y+ky-3,x+kx-3]*w[f,ky,kx]
// B=32, F=64, H=W=224, pad=3. Output fp32 (32,64,224,224).
//
// Strategy: packed f32x2 FMA (fma.rn.f32x2 — 2x fp32 FMA throughput vs FFMA-3reg
// on sm_103a). Block = 14x16 threads, tile = 56x16 pixels x 8 filters.
// Per thread: 4 pixels x 8 filters = 16 packed accumulators.
// 224 = 4*56 = 14*16 exactly -> no bounds checks in hot path.

#define BX 14                 // x-quads per block
#define BY 16                 // y rows per block
#define PX 4                  // pixels per thread (x-consecutive)
#define NF 8                  // filters per block
#define TILE_W (BX * PX)      // 56
#define IN_W (TILE_W + 6)     // 62
#define IN_H (BY + 6)         // 22
#define SROW 72               // smem row stride in floats (breaks row-bank alignment)
#define HH 224
#define WW 224
#define NB 32
#define NFILT 64
#define KSZ 7

__device__ __forceinline__ unsigned long long pack2(float lo, float hi) {
    unsigned long long r;
    asm("mov.b64 %0, {%1, %2};" : "=l"(r) : "f"(lo), "f"(hi));
    return r;
}

__device__ __forceinline__ void ffma2(unsigned long long &d,
                                      unsigned long long a,
                                      unsigned long long b) {
    asm("fma.rn.f32x2 %0, %1, %2, %3;" : "=l"(d) : "l"(a), "l"(b), "l"(d));
}

__device__ __forceinline__ void unpack2(unsigned long long v, float &lo, float &hi) {
    asm("mov.b64 {%0, %1}, %2;" : "=f"(lo), "=f"(hi) : "l"(v));
}

__global__ __launch_bounds__(BX * BY)
void conv7x7_f32x2_kernel(const float* __restrict__ in,
                          const float* __restrict__ wk,
                          float* __restrict__ out) {
    __shared__ __align__(16) float s_in[IN_H * SROW];
    // packed (w,w) weights, layout [k=ky*7+kx][f] so inner loop does LDS.128 broadcast
    __shared__ __align__(16) unsigned long long s_wp[KSZ * KSZ * NF];

    const int x0 = blockIdx.x * TILE_W;
    const int y0 = blockIdx.y * BY;
    const int bz = blockIdx.z;
    const int b  = bz >> 3;        // batch
    const int fg = bz & 7;         // filter group (8 groups of 8)

    const int tid  = threadIdx.y * BX + threadIdx.x;
    const int nthr = BX * BY;      // 224

    // ---- load input tile (with halo, zero-padded) into SMEM ----
    const float* inb = in + (size_t)b * (HH * WW);
    for (int i = tid; i < IN_H * IN_W; i += nthr) {
        int r = i / IN_W, c = i % IN_W;
        int gy = y0 - 3 + r;
        int gx = x0 - 3 + c;
        float v = 0.0f;
        if (gy >= 0 && gy < HH && gx >= 0 && gx < WW)
            v = inb[gy * WW + gx];
        s_in[r * SROW + c] = v;
    }
    // ---- load weights, pre-packed as (w,w) u64 ----
    for (int i = tid; i < KSZ * KSZ * NF; i += nthr) {
        int k = i / NF, f = i % NF;
        float w = wk[(fg * NF + f) * (KSZ * KSZ) + k];
        s_wp[k * NF + f] = pack2(w, w);
    }
    __syncthreads();

    unsigned long long acc[NF][2];
    #pragma unroll
    for (int f = 0; f < NF; f++) { acc[f][0] = 0ull; acc[f][1] = 0ull; }

    const int xl = threadIdx.x * PX;   // local x of first pixel (16B aligned in smem)
    const int yr = threadIdx.y;

    #pragma unroll
    for (int ky = 0; ky < KSZ; ky++) {
        // stage 12 input floats for this row (need t[0..9]) via 3x LDS.128
        float t[12];
        const float4* rp = (const float4*)&s_in[(yr + ky) * SROW + xl];
        float4 a0 = rp[0], a1 = rp[1], a2 = rp[2];
        t[0] = a0.x; t[1]  = a0.y; t[2]  = a0.z; t[3]  = a0.w;
        t[4] = a1.x; t[5]  = a1.y; t[6]  = a1.z; t[7]  = a1.w;
        t[8] = a2.x; t[9]  = a2.y; t[10] = a2.z; t[11] = a2.w;

        #pragma unroll
        for (int kx = 0; kx < KSZ; kx++) {
            unsigned long long p0 = pack2(t[kx],     t[kx + 1]);
            unsigned long long p1 = pack2(t[kx + 2], t[kx + 3]);
            const ulonglong2* wrow =
                (const ulonglong2*)&s_wp[(ky * KSZ + kx) * NF];
            #pragma unroll
            for (int fp = 0; fp < NF / 2; fp++) {
                ulonglong2 wv = wrow[fp];          // broadcast LDS.128, 2 filters
                ffma2(acc[2 * fp][0],     p0, wv.x);
                ffma2(acc[2 * fp][1],     p1, wv.x);
                ffma2(acc[2 * fp + 1][0], p0, wv.y);
                ffma2(acc[2 * fp + 1][1], p1, wv.y);
            }
        }
    }

    // ---- epilogue: unpack + vectorized stores ----
    const int y = y0 + yr;
    const int x = x0 + xl;
    #pragma unroll
    for (int f = 0; f < NF; f++) {
        float4 o;
        unpack2(acc[f][0], o.x, o.y);
        unpack2(acc[f][1], o.z, o.w);
        float* op = out +
            (((size_t)(b * NFILT + fg * NF + f) * HH + y) * WW + x);
        *(float4*)op = o;   // STG.128, 16B aligned (x % 4 == 0)
    }
}

extern "C" void kernel_launch(void* const* d_in, const int* in_sizes, int n_in,
                              void* d_out, int out_size) {
    const float* x = (const float*)d_in[0];   // (32,1,224,224) fp32
    const float* k = (const float*)d_in[1];   // (64,7,7) fp32
    float* out = (float*)d_out;               // (32,64,224,224) fp32

    dim3 block(BX, BY);                        // 224 threads
    dim3 grid(WW / TILE_W, HH / BY, NB * (NFILT / NF));  // (4, 14, 256)
    conv7x7_f32x2_kernel<<<grid, block>>>(x, k, out);
}